// round 15
// baseline (speedup 1.0000x reference)
#include <cuda_runtime.h>
#include <cuda_fp16.h>
#include <cstdint>

// SGIntoKGPool via mma.sync m16n8k16 fp16, single GEMM (x and adj fp16-rn).
// out[b,m,c] = (sum_n adj[b,n,m] * x[b,c,n]) / max(sum_n adj[b,n,m], 1)
// B=8, C=64, N=4096, M=2048.
// Round 15: KT=128 (32 tiles, half the barriers of R14), single 32-reg adj
// prefetch slot issued a full tile ahead, rolling half-tile A-fragment ring,
// __ldcs streaming loads for adj (protect L2-resident A panels).

#define BZv 8
#define Cv  64
#define Nv  4096
#define Mv  2048
#define KT  128
#define NTl (Nv / KT)       // 32 k-tiles
#define MTm 64              // m-tile

#define APANEL   16384       // A tile panel bytes (fp16 fragment order)
#define BSTRIDE  144         // bytes per B smem row (64 halfs + 16B pad)
#define BBUF     (KT * BSTRIDE)             // 18432
#define OFF_DEGS (2 * BBUF)                 // 36864
#define SMEMB    (OFF_DEGS + 256)           // 37120 (static)

// x fp16 fragment panels: per (b,kt): 32 groups (cblk*8+ks) x 32 lanes x uint4 = 16KB
__device__ uint4 g_A[BZv * NTl * 1024];     // 4 MB

__device__ __forceinline__ uint32_t smem_u32(const void* p) {
    uint32_t a;
    asm("{ .reg .u64 t; cvta.to.shared.u64 t, %1; cvt.u32.u64 %0, t; }" : "=r"(a) : "l"(p));
    return a;
}
__device__ __forceinline__ void ldsm4t(uint32_t (&r)[4], uint32_t a) {
    asm volatile("ldmatrix.sync.aligned.m8n8.x4.trans.shared.b16 {%0,%1,%2,%3}, [%4];"
                 : "=r"(r[0]), "=r"(r[1]), "=r"(r[2]), "=r"(r[3]) : "r"(a));
}
__device__ __forceinline__ void mma16816(float (&d)[4], const uint4& a,
                                         uint32_t b0, uint32_t b1) {
    asm volatile("mma.sync.aligned.m16n8k16.row.col.f32.f16.f16.f32 "
                 "{%0,%1,%2,%3}, {%4,%5,%6,%7}, {%8,%9}, {%0,%1,%2,%3};"
                 : "+f"(d[0]), "+f"(d[1]), "+f"(d[2]), "+f"(d[3])
                 : "r"(a.x), "r"(a.y), "r"(a.z), "r"(a.w), "r"(b0), "r"(b1));
}
__device__ __forceinline__ unsigned packh2(float v0, float v1) {
    __half h0 = __float2half_rn(v0), h1 = __float2half_rn(v1);
    return (unsigned)__half_as_ushort(h0) | ((unsigned)__half_as_ushort(h1) << 16);
}
__device__ __forceinline__ void sts128(uint32_t a, uint4 v) {
    asm volatile("st.shared.v4.b32 [%0], {%1,%2,%3,%4};"
                 :: "r"(a), "r"(v.x), "r"(v.y), "r"(v.z), "r"(v.w) : "memory");
}
__device__ __forceinline__ float4 ldcs4(const float* p) {
    float4 v;
    asm volatile("ld.global.cs.v4.f32 {%0,%1,%2,%3}, [%4];"
                 : "=f"(v.x), "=f"(v.y), "=f"(v.z), "=f"(v.w) : "l"(p));
    return v;
}

// ---------------- prep: x -> fp16 fragment panels ----------------
// m16n8k16 A fragment: lane l holds rows {g, g+8} (g=l>>2), cols {2t,2t+1, +8} (t=l&3)
__global__ __launch_bounds__(256)
void prep_A(const float* __restrict__ x) {
    unsigned gid  = blockIdx.x * 256 + threadIdx.x;    // 262144 threads
    unsigned lid  = gid & 31;
    unsigned ks   = (gid >> 5) & 7;
    unsigned cblk = (gid >> 8) & 3;
    unsigned kt   = (gid >> 10) & (NTl - 1);
    unsigned b    = gid >> 15;

    int r0 = cblk * 16 + (lid >> 2);                   // c row
    const float* px = x + ((size_t)b * Cv + r0) * Nv + kt * KT + ks * 16 + (lid & 3) * 2;

    uint4 f;
    f.x = packh2(px[0],          px[1]);
    f.y = packh2(px[8 * Nv],     px[8 * Nv + 1]);
    f.z = packh2(px[8],          px[9]);
    f.w = packh2(px[8 * Nv + 8], px[8 * Nv + 9]);

    g_A[((size_t)(b * NTl + kt) << 10) + (cblk * 8 + ks) * 32 + lid] = f;
}

// ---------------- main kernel ----------------
__global__ __launch_bounds__(256, 2)
void sg_kg_fp16(const float* __restrict__ adj, float* __restrict__ out) {
    __shared__ __align__(16) char smem[SMEMB];
    const int tid = threadIdx.x;
    const int lid = tid & 31, wid = tid >> 5;
    const int b = blockIdx.y, m0 = blockIdx.x * MTm;
    const int cblk = wid & 3;        // c dir: 4 warps x 16 rows
    const int wc   = wid >> 2;       // m dir: 2 warps x 32 cols
    const uint32_t sb = smem_u32(smem);

    // adj lane mapping: thread owns rows {q, q+32, q+64, q+96}, m chunk mq*8..+7
    const int q  = tid >> 3;         // 0..31
    const int mq = tid & 7;
    const float* adjb = adj + (size_t)b * Nv * Mv + m0 + mq * 8;

    const char* Apan = (const char*)g_A + (size_t)(b * NTl) * APANEL + lid * 16;

    float* degS = (float*)(smem + OFF_DEGS);
    if (tid < MTm) degS[tid] = 0.0f;

    float acc[4][4];
    #pragma unroll
    for (int j = 0; j < 4; j++)
        #pragma unroll
        for (int p = 0; p < 4; p++) acc[j][p] = 0.f;
    float dacc[8] = {0,0,0,0,0,0,0,0};

    // B ldsm per-thread offset (+ks*16 rows per k-step)
    const uint32_t bl = (uint32_t)((lid & 15) * BSTRIDE + (wc * 32 + (lid >> 4) * 8) * 2);
    // A fragment byte offset: group g = cblk*8 + ks, offset g*512 (+lid*16 in Apan)
    const uint32_t ag = (uint32_t)(cblk * 8) * 512;

    // single-slot adj prefetch: 4 rows x 2 float4 = 32 regs
    float4 fr[4][2];
    auto loadAdj = [&](int t) {
        #pragma unroll
        for (int i = 0; i < 4; i++) {
            const float* g = adjb + (size_t)(t * KT + q + 32 * i) * Mv;
            fr[i][0] = ldcs4(g);
            fr[i][1] = ldcs4(g + 4);
        }
    };
    auto stageB = [&](int bufsel) {
        #pragma unroll
        for (int i = 0; i < 4; i++) {
            float4 f0 = fr[i][0], f1 = fr[i][1];
            dacc[0] += f0.x; dacc[1] += f0.y; dacc[2] += f0.z; dacc[3] += f0.w;
            dacc[4] += f1.x; dacc[5] += f1.y; dacc[6] += f1.z; dacc[7] += f1.w;
            uint4 w = make_uint4(packh2(f0.x, f0.y), packh2(f0.z, f0.w),
                                 packh2(f1.x, f1.y), packh2(f1.z, f1.w));
            sts128(sb + bufsel * BBUF + (q + 32 * i) * BSTRIDE + mq * 16, w);
        }
    };

    // rolling A-fragment ring: 4 slots (half tile), R8 pattern
    uint4 afr[4];
    #pragma unroll
    for (int s = 0; s < 4; s++)
        afr[s] = *(const uint4*)(Apan + ag + s * 512);

    // prologue: stage tile 0, prefetch tile 1
    loadAdj(0);
    stageB(0);
    loadAdj(1);
    __syncthreads();

    for (int t = 0; t < NTl; t++) {
        // stage tile t+1 (fr), then refill fr with tile t+2
        if (t + 1 < NTl) stageB((t + 1) & 1);
        if (t + 2 < NTl) loadAdj(t + 2);

        const char* Acur  = Apan + (size_t)t * APANEL;
        const char* Anext = Apan + (size_t)((t + 1 < NTl) ? t + 1 : t) * APANEL;
        const uint32_t sB = sb + (t & 1) * BBUF + bl;

        #pragma unroll
        for (int ks = 0; ks < 8; ks++) {
            const int slot = ks & 3;
            uint32_t bb0[4], bb1[4];
            ldsm4t(bb0, sB + ks * (16 * BSTRIDE));         // n 0..15 of warp half
            ldsm4t(bb1, sB + ks * (16 * BSTRIDE) + 32);    // n 16..31
            uint4 a = afr[slot];
            // refill slot: ks+4 of this tile, or ks-4 of next tile
            const char* Asrc = (ks < 4) ? Acur : Anext;
            const int kk = (ks < 4) ? ks + 4 : ks - 4;
            afr[slot] = *(const uint4*)(Asrc + ag + kk * 512);
            mma16816(acc[0], a, bb0[0], bb0[1]); mma16816(acc[1], a, bb0[2], bb0[3]);
            mma16816(acc[2], a, bb1[0], bb1[1]); mma16816(acc[3], a, bb1[2], bb1[3]);
        }

        __syncthreads();     // buf (t+1)&1 visible; tile-t buffer reads complete
    }

    // ---- degrees: exact fp32, smem atomic reduction ----
    #pragma unroll
    for (int j = 0; j < 4; j++) {
        atomicAdd(&degS[mq * 8 + j],     dacc[j]);
        atomicAdd(&degS[mq * 8 + 4 + j], dacc[4 + j]);
    }

    // ---- stage accumulators (outS aliases B buffers; disjoint from degS) ----
    float* outS = (float*)smem;      // [m][c], stride 68 floats (17408 B)
    #pragma unroll
    for (int nb = 0; nb < 4; nb++) {
        int c_row = cblk * 16 + (lid >> 2);
        int m_col = wc * 32 + nb * 8 + (lid & 3) * 2;
        outS[m_col * 68 + c_row]           = acc[nb][0];
        outS[(m_col + 1) * 68 + c_row]     = acc[nb][1];
        outS[m_col * 68 + c_row + 8]       = acc[nb][2];
        outS[(m_col + 1) * 68 + c_row + 8] = acc[nb][3];
    }
    __syncthreads();

    // ---- scaled float4 stores ----
    float* Og = out + ((size_t)b * Mv + m0) * Cv;
    #pragma unroll
    for (int i = 0; i < 4; i++) {
        int idx = tid + i * 256;                 // 1024 float4s
        int ml = idx >> 4, c4 = (idx & 15) * 4;
        float4 v = *(float4*)(outS + ml * 68 + c4);
        float inv = __frcp_rn(fmaxf(degS[ml], 1.0f));
        v.x *= inv; v.y *= inv; v.z *= inv; v.w *= inv;
        *(float4*)(Og + (size_t)ml * Cv + c4) = v;
    }
}

extern "C" void kernel_launch(void* const* d_in, const int* in_sizes, int n_in,
                              void* d_out, int out_size)
{
    const float* x;
    const float* adj;
    if (in_sizes[0] == BZv * Cv * Nv) {
        x   = (const float*)d_in[0];
        adj = (const float*)d_in[1];
    } else {
        x   = (const float*)d_in[1];
        adj = (const float*)d_in[0];
    }
    float* out = (float*)d_out;

    prep_A<<<1024, 256>>>(x);                                // 262144 threads
    sg_kg_fp16<<<dim3(Mv / MTm, BZv), 256>>>(adj, out);      // 32 x 8 = 256 CTAs
}

// round 16
// speedup vs baseline: 1.0374x; 1.0374x over previous
#include <cuda_runtime.h>
#include <cuda_fp16.h>
#include <cstdint>

// SGIntoKGPool via mma.sync m16n8k16 fp16, single GEMM (x and adj fp16-rn).
// out[b,m,c] = (sum_n adj[b,n,m] * x[b,c,n]) / max(sum_n adj[b,n,m], 1)
// B=8, C=64, N=4096, M=2048.
// Round 16: R14 + prefetch depth 3 — three adj register slots and THREE smem
// B buffers (all indices mod-3, compile-time via unroll 3). 48KB/CTA of adj
// in flight, loads issued ~3 tile-times ahead. __ldcs streaming on adj.

#define BZv 8
#define Cv  64
#define Nv  4096
#define Mv  2048
#define KT  64
#define NTl (Nv / KT)       // 64 k-tiles
#define MTm 64              // m-tile

#define APANEL   8192        // A tile panel bytes (fp16 fragment order)
#define BSTRIDE  144         // bytes per B smem row (64 halfs + 16B pad)
#define BBUF     (KT * BSTRIDE)             // 9216
#define OFF_DEGS (3 * BBUF)                 // 27648
#define SMEMB    (OFF_DEGS + 256)           // 27904 (static; 2 CTAs/SM)

// x fp16 fragment panels: per (b,kt): 16 groups (cblk*4+ks) x 32 lanes x uint4 = 8KB
__device__ uint4 g_A[BZv * NTl * 512];      // 4 MB

__device__ __forceinline__ uint32_t smem_u32(const void* p) {
    uint32_t a;
    asm("{ .reg .u64 t; cvta.to.shared.u64 t, %1; cvt.u32.u64 %0, t; }" : "=r"(a) : "l"(p));
    return a;
}
__device__ __forceinline__ void ldsm4t(uint32_t (&r)[4], uint32_t a) {
    asm volatile("ldmatrix.sync.aligned.m8n8.x4.trans.shared.b16 {%0,%1,%2,%3}, [%4];"
                 : "=r"(r[0]), "=r"(r[1]), "=r"(r[2]), "=r"(r[3]) : "r"(a));
}
__device__ __forceinline__ void mma16816(float (&d)[4], const uint4& a,
                                         uint32_t b0, uint32_t b1) {
    asm volatile("mma.sync.aligned.m16n8k16.row.col.f32.f16.f16.f32 "
                 "{%0,%1,%2,%3}, {%4,%5,%6,%7}, {%8,%9}, {%0,%1,%2,%3};"
                 : "+f"(d[0]), "+f"(d[1]), "+f"(d[2]), "+f"(d[3])
                 : "r"(a.x), "r"(a.y), "r"(a.z), "r"(a.w), "r"(b0), "r"(b1));
}
__device__ __forceinline__ unsigned packh2(float v0, float v1) {
    __half h0 = __float2half_rn(v0), h1 = __float2half_rn(v1);
    return (unsigned)__half_as_ushort(h0) | ((unsigned)__half_as_ushort(h1) << 16);
}
__device__ __forceinline__ void sts128(uint32_t a, uint4 v) {
    asm volatile("st.shared.v4.b32 [%0], {%1,%2,%3,%4};"
                 :: "r"(a), "r"(v.x), "r"(v.y), "r"(v.z), "r"(v.w) : "memory");
}
__device__ __forceinline__ float4 ldcs4(const float* p) {
    float4 v;
    asm volatile("ld.global.cs.v4.f32 {%0,%1,%2,%3}, [%4];"
                 : "=f"(v.x), "=f"(v.y), "=f"(v.z), "=f"(v.w) : "l"(p));
    return v;
}

// ---------------- prep: x -> fp16 fragment panels ----------------
// m16n8k16 A fragment: lane l holds rows {g, g+8} (g=l>>2), cols {2t,2t+1, +8} (t=l&3)
__global__ __launch_bounds__(256)
void prep_A(const float* __restrict__ x) {
    unsigned gid  = blockIdx.x * 256 + threadIdx.x;    // 262144 threads
    unsigned lid  = gid & 31;
    unsigned ks   = (gid >> 5) & 3;
    unsigned cblk = (gid >> 7) & 3;
    unsigned kt   = (gid >> 9) & (NTl - 1);
    unsigned b    = gid >> 15;

    int r0 = cblk * 16 + (lid >> 2);                   // c row
    const float* px = x + ((size_t)b * Cv + r0) * Nv + kt * KT + ks * 16 + (lid & 3) * 2;

    uint4 f;
    f.x = packh2(px[0],          px[1]);
    f.y = packh2(px[8 * Nv],     px[8 * Nv + 1]);
    f.z = packh2(px[8],          px[9]);
    f.w = packh2(px[8 * Nv + 8], px[8 * Nv + 9]);

    g_A[((size_t)(b * NTl + kt) << 9) + (cblk * 4 + ks) * 32 + lid] = f;
}

// ---------------- main kernel ----------------
__global__ __launch_bounds__(256, 2)
void sg_kg_fp16(const float* __restrict__ adj, float* __restrict__ out) {
    __shared__ __align__(16) char smem[SMEMB];
    const int tid = threadIdx.x;
    const int lid = tid & 31, wid = tid >> 5;
    const int b = blockIdx.y, m0 = blockIdx.x * MTm;
    const int cblk = wid & 3;        // c dir: 4 warps x 16 rows
    const int wc   = wid >> 2;       // m dir: 2 warps x 32 cols
    const uint32_t sb = smem_u32(smem);

    // adj lane mapping: thread owns k-rows r, r+32; m chunk mq*8..+7
    const int r  = tid >> 3;         // 0..31
    const int mq = tid & 7;
    const float* adjb = adj + (size_t)b * Nv * Mv + m0 + mq * 8;

    const char* Apan = (const char*)g_A + (size_t)(b * NTl) * APANEL + lid * 16;

    float* degS = (float*)(smem + OFF_DEGS);
    if (tid < MTm) degS[tid] = 0.0f;

    float acc[4][4];
    #pragma unroll
    for (int j = 0; j < 4; j++)
        #pragma unroll
        for (int p = 0; p < 4; p++) acc[j][p] = 0.f;
    float dacc[8] = {0,0,0,0,0,0,0,0};

    // B ldsm per-thread offset (+ks*16 rows per k-step)
    const uint32_t bl = (uint32_t)((lid & 15) * BSTRIDE + (wc * 32 + (lid >> 4) * 8) * 2);
    // A fragment byte offset: group g = cblk*4 + ks, offset g*512 (+lid*16 in Apan)
    const uint32_t ag = (uint32_t)(cblk * 4) * 512;

    // triple-buffered adj register prefetch: slot = tile % 3
    float4 fr[3][4];

    auto loadAdjS = [&](int slot, int t) {
        const float* g = adjb + (size_t)(t * KT + r) * Mv;
        fr[slot][0] = ldcs4(g);
        fr[slot][1] = ldcs4(g + 4);
        const float* g2 = g + (size_t)32 * Mv;
        fr[slot][2] = ldcs4(g2);
        fr[slot][3] = ldcs4(g2 + 4);
    };
    auto stageBS = [&](int slot, int bufsel) {
        float4 f0 = fr[slot][0], f1 = fr[slot][1];
        float4 f2 = fr[slot][2], f3 = fr[slot][3];
        dacc[0] += f0.x + f2.x; dacc[1] += f0.y + f2.y;
        dacc[2] += f0.z + f2.z; dacc[3] += f0.w + f2.w;
        dacc[4] += f1.x + f3.x; dacc[5] += f1.y + f3.y;
        dacc[6] += f1.z + f3.z; dacc[7] += f1.w + f3.w;
        uint32_t s = sb + bufsel * BBUF + r * BSTRIDE + mq * 16;
        uint4 w0 = make_uint4(packh2(f0.x, f0.y), packh2(f0.z, f0.w),
                              packh2(f1.x, f1.y), packh2(f1.z, f1.w));
        uint4 w1 = make_uint4(packh2(f2.x, f2.y), packh2(f2.z, f2.w),
                              packh2(f3.x, f3.y), packh2(f3.z, f3.w));
        sts128(s, w0);
        sts128(s + 32 * BSTRIDE, w1);
    };

    // A fragments for current tile (one uint4 per ks)
    uint4 afr[4];
    #pragma unroll
    for (int ks = 0; ks < 4; ks++)
        afr[ks] = *(const uint4*)(Apan + ag + ks * 512);

    // prologue: stage tile 0 into buf 0; tiles 1,2,3 in flight (slots 1,2,0)
    loadAdjS(0, 0);
    stageBS(0, 0);
    loadAdjS(1, 1);
    loadAdjS(2, 2);
    loadAdjS(0, 3);
    __syncthreads();

    // main loop: iters 0..62 (multiple of 3 -> mod-3 indices compile-time)
    #pragma unroll 3
    for (int t = 0; t < NTl - 1; t++) {
        const int sN = (t + 1) % 3;              // slot & buf for tile t+1
        // stage tile t+1 (buf sN last read at iter t-2; barrier passed),
        // then refill the freed slot with tile t+4.
        stageBS(sN, sN);
        if (t + 4 < NTl) loadAdjS(sN, t + 4);

        const char* Anext = Apan + (size_t)(t + 1) * APANEL;
        const uint32_t sB = sb + (t % 3) * BBUF + bl;

        #pragma unroll
        for (int ks = 0; ks < 4; ks++) {
            uint32_t bb0[4], bb1[4];
            ldsm4t(bb0, sB + ks * (16 * BSTRIDE));         // n 0..15 of warp half
            ldsm4t(bb1, sB + ks * (16 * BSTRIDE) + 32);    // n 16..31
            uint4 a = afr[ks];
            afr[ks] = *(const uint4*)(Anext + ag + ks * 512);   // full-tile refill slack
            mma16816(acc[0], a, bb0[0], bb0[1]); mma16816(acc[1], a, bb0[2], bb0[3]);
            mma16816(acc[2], a, bb1[0], bb1[1]); mma16816(acc[3], a, bb1[2], bb1[3]);
        }

        __syncthreads();     // buf sN visible; tile-t buffer reads complete
    }

    // tail: tile 63 (buf 63 % 3 = 0), no staging, no loads
    {
        const uint32_t sB = sb + ((NTl - 1) % 3) * BBUF + bl;
        #pragma unroll
        for (int ks = 0; ks < 4; ks++) {
            uint32_t bb0[4], bb1[4];
            ldsm4t(bb0, sB + ks * (16 * BSTRIDE));
            ldsm4t(bb1, sB + ks * (16 * BSTRIDE) + 32);
            uint4 a = afr[ks];
            mma16816(acc[0], a, bb0[0], bb0[1]); mma16816(acc[1], a, bb0[2], bb0[3]);
            mma16816(acc[2], a, bb1[0], bb1[1]); mma16816(acc[3], a, bb1[2], bb1[3]);
        }
        __syncthreads();
    }

    // ---- degrees: exact fp32, smem atomic reduction ----
    #pragma unroll
    for (int j = 0; j < 4; j++) {
        atomicAdd(&degS[mq * 8 + j],     dacc[j]);
        atomicAdd(&degS[mq * 8 + 4 + j], dacc[4 + j]);
    }

    // ---- stage accumulators (outS aliases B buffers; disjoint from degS) ----
    float* outS = (float*)smem;      // [m][c], stride 68 floats (17408 B)
    #pragma unroll
    for (int nb = 0; nb < 4; nb++) {
        int c_row = cblk * 16 + (lid >> 2);
        int m_col = wc * 32 + nb * 8 + (lid & 3) * 2;
        outS[m_col * 68 + c_row]           = acc[nb][0];
        outS[(m_col + 1) * 68 + c_row]     = acc[nb][1];
        outS[m_col * 68 + c_row + 8]       = acc[nb][2];
        outS[(m_col + 1) * 68 + c_row + 8] = acc[nb][3];
    }
    __syncthreads();

    // ---- scaled float4 stores ----
    float* Og = out + ((size_t)b * Mv + m0) * Cv;
    #pragma unroll
    for (int i = 0; i < 4; i++) {
        int idx = tid + i * 256;                 // 1024 float4s
        int ml = idx >> 4, c4 = (idx & 15) * 4;
        float4 v = *(float4*)(outS + ml * 68 + c4);
        float inv = __frcp_rn(fmaxf(degS[ml], 1.0f));
        v.x *= inv; v.y *= inv; v.z *= inv; v.w *= inv;
        *(float4*)(Og + (size_t)ml * Cv + c4) = v;
    }
}

extern "C" void kernel_launch(void* const* d_in, const int* in_sizes, int n_in,
                              void* d_out, int out_size)
{
    const float* x;
    const float* adj;
    if (in_sizes[0] == BZv * Cv * Nv) {
        x   = (const float*)d_in[0];
        adj = (const float*)d_in[1];
    } else {
        x   = (const float*)d_in[1];
        adj = (const float*)d_in[0];
    }
    float* out = (float*)d_out;

    prep_A<<<1024, 256>>>(x);                                // 262144 threads
    sg_kg_fp16<<<dim3(Mv / MTm, BZv), 256>>>(adj, out);      // 32 x 8 = 256 CTAs
}